// round 7
// baseline (speedup 1.0000x reference)
#include <cuda_runtime.h>
#include <cuda_bf16.h>
#include <cstdint>

#define NN  100000
#define EE  800000
#define DD  96
#define NRD 102   // D + XD

typedef unsigned long long u64;

__device__ __forceinline__ u64 pk2(float lo, float hi) {
    u64 r; asm("mov.b64 %0,{%1,%2};" : "=l"(r) : "f"(lo), "f"(hi)); return r;
}
__device__ __forceinline__ u64 ffma2(u64 a, u64 b, u64 c) {
    u64 d; asm("fma.rn.f32x2 %0,%1,%2,%3;" : "=l"(d) : "l"(a), "l"(b), "l"(c)); return d;
}
__device__ __forceinline__ float2 up2(u64 v) {
    float2 f; asm("mov.b64 {%0,%1},%2;" : "=f"(f.x), "=f"(f.y) : "l"(v)); return f;
}
__device__ __forceinline__ uint32_t smem_u32(const void* p) {
    uint32_t a;
    asm("{ .reg .u64 t; cvta.to.shared.u64 t, %1; cvt.u32.u64 %0, t; }" : "=r"(a) : "l"(p));
    return a;
}

// ---- scratch (device globals; no allocation allowed) ----
__device__ __align__(16) float4 g_num4[NN * 24];
__device__ float  g_den[NN];
__device__ __align__(16) float g_P[NN * DD];
__device__ __align__(16) float g_Q[NN * DD];
__device__ __align__(16) uint4 g_W3hi[96 * 192 / 16];   // bf16 [96 o][96 k]
__device__ __align__(16) uint4 g_W3lo[96 * 192 / 16];

// ---------------------------------------------------------------------------
// bf16 split helpers (cvt.rn.bf16x2.f32: 2 elems per instruction)
// ---------------------------------------------------------------------------
__device__ __forceinline__ void split4(float4 v, uint2& hi, uint2& lo) {
    uint32_t h01, h23, l01, l23;
    asm("cvt.rn.bf16x2.f32 %0, %1, %2;" : "=r"(h01) : "f"(v.y), "f"(v.x));
    asm("cvt.rn.bf16x2.f32 %0, %1, %2;" : "=r"(h23) : "f"(v.w), "f"(v.z));
    float r0 = v.x - __uint_as_float(h01 << 16);
    float r1 = v.y - __uint_as_float(h01 & 0xFFFF0000u);
    float r2 = v.z - __uint_as_float(h23 << 16);
    float r3 = v.w - __uint_as_float(h23 & 0xFFFF0000u);
    asm("cvt.rn.bf16x2.f32 %0, %1, %2;" : "=r"(l01) : "f"(r1), "f"(r0));
    asm("cvt.rn.bf16x2.f32 %0, %1, %2;" : "=r"(l23) : "f"(r3), "f"(r2));
    hi = make_uint2(h01, h23); lo = make_uint2(l01, l23);
}

// ---------------------------------------------------------------------------
// K0: zero accumulators, write x cols, block 0 also splits W3 to bf16 hi/lo
// ---------------------------------------------------------------------------
__global__ void init_k(const float* __restrict__ x, float* __restrict__ node_out,
                       const float* __restrict__ W) {
    if (blockIdx.x == 0) {
        for (int i = threadIdx.x; i < 96 * 24; i += 256) {
            int o = i / 24, q = i % 24;
            float4 v = *(const float4*)(W + o * 300 + 204 + q * 4);
            uint2 hi, lo;
            split4(v, hi, lo);
            *((uint2*)g_W3hi + o * 24 + q) = hi;
            *((uint2*)g_W3lo + o * 24 + q) = lo;
        }
    }
    int i = blockIdx.x * 256 + threadIdx.x;
    if (i < NN * 24) g_num4[i] = make_float4(0.f, 0.f, 0.f, 0.f);
    if (i < NN)      g_den[i] = 0.f;
    if (i < NN * 6)  node_out[(i / 6) * NRD + 96 + (i % 6)] = x[i];
}

// ---------------------------------------------------------------------------
__global__ void scatter_k(const int* __restrict__ ei,
                          const float* __restrict__ attr,
                          const float* __restrict__ mask) {
    int i = blockIdx.x * 256 + threadIdx.x;
    if (i >= EE * 24) return;
    int e = i / 24;
    int q = i - e * 24;
    int c = ei[EE + e];
    float m = mask[e];
    float4 v = *(const float4*)(attr + (size_t)e * 96 + q * 4);
    float* dst = ((float*)g_num4) + (size_t)c * 96 + q * 4;
    asm volatile("red.global.add.v4.f32 [%0], {%1,%2,%3,%4};"
                 :: "l"(dst), "f"(v.x * m), "f"(v.y * m), "f"(v.z * m), "f"(v.w * m)
                 : "memory");
    if (q == 0) atomicAdd(&g_den[c], m);
}

// ---------------------------------------------------------------------------
__global__ void finalize_k(float* __restrict__ node_out) {
    int i = blockIdx.x * 256 + threadIdx.x;
    if (i >= NN * 24) return;
    int n = i / 24;
    int q = i - n * 24;
    float inv = 1.f / (g_den[n] + 1.f);
    float4 v = g_num4[i];
    float* dst = node_out + (size_t)n * NRD + q * 4;
    dst[0] = v.x * inv; dst[1] = v.y * inv; dst[2] = v.z * inv; dst[3] = v.w * inv;
}

// ---------------------------------------------------------------------------
__global__ void blend_k(const int* __restrict__ change,
                        const int* __restrict__ is_support,
                        const int* __restrict__ tails,
                        const float* __restrict__ support_tail,
                        float* __restrict__ node_out) {
    if (change[0] == 0) return;
    const int TOT = 128 * NRD;
    int tid = threadIdx.x;
    float vals[13];
    int   addr[13];
    short dim[13];
    int cnt = 0;
    for (int i = tid; i < TOT; i += 1024) {
        int t = i / NRD, d = i - t * NRD;
        int node = tails[t];
        addr[cnt] = node * NRD + d;
        dim[cnt]  = (short)d;
        vals[cnt] = node_out[addr[cnt]];
        cnt++;
    }
    if (is_support[0]) {
        __shared__ float ssum[NRD];
        for (int d = tid; d < NRD; d += 1024) ssum[d] = 0.f;
        __syncthreads();
        for (int j = 0; j < cnt; j++) atomicAdd(&ssum[dim[j]], vals[j]);
        __syncthreads();
        for (int j = 0; j < cnt; j++)
            node_out[addr[j]] = ssum[dim[j]] * (1.f / 128.f);
    } else {
        __syncthreads();
        for (int j = 0; j < cnt; j++)
            node_out[addr[j]] = 0.1f * support_tail[dim[j]] + 0.9f * vals[j];
    }
}

// ---------------------------------------------------------------------------
// K4: P/Q GEMM — proven R2 version
// ---------------------------------------------------------------------------
__global__ __launch_bounds__(256) void pq_gemm(const float* __restrict__ node_rep,
                                               const float* __restrict__ W) {
    __shared__ __align__(16) float sW[NRD][98];
    __shared__ __align__(16) float sA[64][35];
    int tid = threadIdx.x;
    int z = blockIdx.z;
    int n0 = blockIdx.x * 64;
    const float* Wz = W + z * NRD;

    for (int i = tid; i < NRD * 96; i += 256) {
        int k = i % NRD, o = i / NRD;
        sW[k][o] = Wz[o * 300 + k];
    }

    u64 acc[4][3] = {};
    int ty = tid >> 4;
    int tx = tid & 15;

    for (int k0 = 0; k0 < NRD; k0 += 34) {
        __syncthreads();
        #pragma unroll
        for (int v = 0; v < 5; v++) {
            int f = tid + v * 256;
            if (f < 64 * 17) {
                int e = f / 17;
                int kk2 = (f - e * 17) * 2;
                int n = n0 + e;
                float2 val = (n < NN)
                    ? *(const float2*)(node_rep + (size_t)n * NRD + k0 + kk2)
                    : make_float2(0.f, 0.f);
                sA[e][kk2] = val.x; sA[e][kk2 + 1] = val.y;
            }
        }
        __syncthreads();
        #pragma unroll
        for (int kk = 0; kk < 34; kk++) {
            const u64* wp = (const u64*)&sW[k0 + kk][tx * 6];
            u64 w0 = wp[0], w1 = wp[1], w2 = wp[2];
            #pragma unroll
            for (int i2 = 0; i2 < 4; i2++) {
                float a = sA[ty * 4 + i2][kk];
                u64 ap = pk2(a, a);
                acc[i2][0] = ffma2(ap, w0, acc[i2][0]);
                acc[i2][1] = ffma2(ap, w1, acc[i2][1]);
                acc[i2][2] = ffma2(ap, w2, acc[i2][2]);
            }
        }
    }

    float* out = z ? g_Q : g_P;
    #pragma unroll
    for (int i2 = 0; i2 < 4; i2++) {
        int n = n0 + ty * 4 + i2;
        if (n < NN) {
            float2* dst = (float2*)(out + (size_t)n * 96 + tx * 6);
            #pragma unroll
            for (int j2 = 0; j2 < 3; j2++) dst[j2] = up2(acc[i2][j2]);
        }
    }
}

// ---------------------------------------------------------------------------
// K5: edge_rep via mma.sync bf16 3-term split — FULL-TILE single-sync version.
//   smem: A hi/lo 128x96 bf16 (RS2=208B rows) + B hi/lo 96x96 bf16. 93KB dyn.
//   Load phase: 12+9 LDG.128 per thread front-issued (MLP high), 1 sync,
//   then 216 HMMAs uninterrupted.
// ---------------------------------------------------------------------------
#define RS2 208          // 192B data + 16B pad; 8-row stride pattern conflict-free

__device__ __forceinline__ void ldsm4(uint32_t addr, uint32_t* r) {
    asm volatile("ldmatrix.sync.aligned.m8n8.x4.shared.b16 {%0,%1,%2,%3}, [%4];"
                 : "=r"(r[0]), "=r"(r[1]), "=r"(r[2]), "=r"(r[3]) : "r"(addr));
}
__device__ __forceinline__ void mma_bf16(float4& c, const uint32_t* a,
                                         uint32_t b0, uint32_t b1) {
    asm volatile(
        "mma.sync.aligned.m16n8k16.row.col.f32.bf16.bf16.f32 "
        "{%0,%1,%2,%3}, {%4,%5,%6,%7}, {%8,%9}, {%0,%1,%2,%3};"
        : "+f"(c.x), "+f"(c.y), "+f"(c.z), "+f"(c.w)
        : "r"(a[0]), "r"(a[1]), "r"(a[2]), "r"(a[3]), "r"(b0), "r"(b1));
}

#define SM_AHI 0
#define SM_ALO (128 * RS2)
#define SM_BHI (2 * 128 * RS2)
#define SM_BLO (2 * 128 * RS2 + 96 * RS2)
#define SM_TOT (2 * 128 * RS2 + 2 * 96 * RS2)   // 93184 B

__global__ __launch_bounds__(256, 1) void edge_mma(const float* __restrict__ attr,
                                                   const float* __restrict__ b,
                                                   const int* __restrict__ ei,
                                                   float* __restrict__ out) {
    extern __shared__ __align__(16) char smem[];
    int tid = threadIdx.x, lane = tid & 31, w = tid >> 5;
    size_t e0 = (size_t)blockIdx.x * 128;

    // ---- load + convert A full tile: 128 rows x 96 k (3072 float4 quads) ----
    #pragma unroll
    for (int v = 0; v < 12; v++) {
        int f = tid + v * 256;
        int r = f / 24, q4 = f % 24;
        float4 val = *(const float4*)(attr + (e0 + r) * 96 + q4 * 4);
        uint2 hi, lo;
        split4(val, hi, lo);
        int off = r * RS2 + q4 * 8;
        *(uint2*)(smem + SM_AHI + off) = hi;
        *(uint2*)(smem + SM_ALO + off) = lo;
    }
    // ---- copy pre-split B: 2 arrays x 96 rows x 12 uint4 = 2304 ----
    #pragma unroll
    for (int v = 0; v < 9; v++) {
        int f = tid + v * 256;
        int sel = f >= 1152;
        int g = sel ? f - 1152 : f;
        int o = g / 12, q = g % 12;
        uint4 val = (sel ? g_W3lo : g_W3hi)[o * 12 + q];
        *(uint4*)(smem + (sel ? SM_BLO : SM_BHI) + o * RS2 + q * 16) = val;
    }
    __syncthreads();

    uint32_t aHi = smem_u32(smem) + SM_AHI, aLo = smem_u32(smem) + SM_ALO;
    uint32_t bHi = smem_u32(smem) + SM_BHI, bLo = smem_u32(smem) + SM_BLO;

    uint32_t aoff = (uint32_t)(w * 16 + (lane & 15)) * RS2 + ((lane >> 4) & 1) * 16;
    uint32_t boff = ((lane >> 4) & 1) * 8 * RS2 + (uint32_t)(lane & 7) * RS2
                  + ((lane >> 3) & 1) * 16;

    float4 acc[12];
    #pragma unroll
    for (int t = 0; t < 12; t++) acc[t] = make_float4(0.f, 0.f, 0.f, 0.f);

    #pragma unroll
    for (int kc16 = 0; kc16 < 6; kc16++) {
        uint32_t ah[4], al[4];
        ldsm4(aHi + aoff + kc16 * 32, ah);
        ldsm4(aLo + aoff + kc16 * 32, al);
        #pragma unroll
        for (int tp = 0; tp < 6; tp++) {
            uint32_t bh[4], bl[4];
            uint32_t bo = (uint32_t)(tp * 16) * RS2 + boff + kc16 * 32;
            ldsm4(bHi + bo, bh);
            ldsm4(bLo + bo, bl);
            mma_bf16(acc[tp * 2],     ah, bh[0], bh[1]);
            mma_bf16(acc[tp * 2],     ah, bl[0], bl[1]);
            mma_bf16(acc[tp * 2],     al, bh[0], bh[1]);
            mma_bf16(acc[tp * 2 + 1], ah, bh[2], bh[3]);
            mma_bf16(acc[tp * 2 + 1], ah, bl[2], bl[3]);
            mma_bf16(acc[tp * 2 + 1], al, bh[2], bh[3]);
        }
    }

    // epilogue: thread owns rows mrow, mrow+8; cols t*8 + kq*2
    int mrow = w * 16 + (lane >> 2);
    int kq = lane & 3;
    int er0 = (int)e0 + mrow;
    int er1 = er0 + 8;
    int r0i = ei[er0], c0i = ei[EE + er0];
    int r1i = ei[er1], c1i = ei[EE + er1];
    const float* P0 = g_P + (size_t)r0i * 96;
    const float* Q0 = g_Q + (size_t)c0i * 96;
    const float* P1 = g_P + (size_t)r1i * 96;
    const float* Q1 = g_Q + (size_t)c1i * 96;
    float* o0 = out + (size_t)er0 * 96;
    float* o1 = out + (size_t)er1 * 96;
    #pragma unroll
    for (int t = 0; t < 12; t++) {
        int col = t * 8 + kq * 2;
        float2 bv = *(const float2*)(b + col);
        float2 p0 = *(const float2*)(P0 + col), q0 = *(const float2*)(Q0 + col);
        *(float2*)(o0 + col) = make_float2(acc[t].x + p0.x + q0.x + bv.x,
                                           acc[t].y + p0.y + q0.y + bv.y);
        float2 p1 = *(const float2*)(P1 + col), q1 = *(const float2*)(Q1 + col);
        *(float2*)(o1 + col) = make_float2(acc[t].z + p1.x + q1.x + bv.x,
                                           acc[t].w + p1.y + q1.y + bv.y);
    }
}

// ---------------------------------------------------------------------------
extern "C" void kernel_launch(void* const* d_in, const int* in_sizes, int n_in,
                              void* d_out, int out_size) {
    const int*   change = (const int*)d_in[0];
    const int*   is_sup = (const int*)d_in[1];
    const int*   tails  = (const int*)d_in[3];
    const float* x      = (const float*)d_in[4];
    const int*   ei     = (const int*)d_in[5];
    const float* attr   = (const float*)d_in[6];
    const float* mask   = (const float*)d_in[7];
    const float* stail  = (const float*)d_in[9];
    const float* W      = (const float*)d_in[10];
    const float* b      = (const float*)d_in[11];

    float* node_out = (float*)d_out;
    float* edge_out = node_out + (size_t)NN * NRD;

    static int smem_set = 0;
    if (!smem_set) {
        cudaFuncSetAttribute(edge_mma, cudaFuncAttributeMaxDynamicSharedMemorySize, SM_TOT);
        smem_set = 1;
    }

    init_k    <<<(NN * 24 + 255) / 256, 256>>>(x, node_out, W);
    scatter_k <<<(EE * 24 + 255) / 256, 256>>>(ei, attr, mask);
    finalize_k<<<(NN * 24 + 255) / 256, 256>>>(node_out);
    blend_k   <<<1, 1024>>>(change, is_sup, tails, stail, node_out);
    pq_gemm   <<<dim3((NN + 63) / 64, 1, 2), 256>>>(node_out, W);
    edge_mma  <<<EE / 128, 256, SM_TOT>>>(attr, b, ei, edge_out);
}

// round 8
// speedup vs baseline: 1.2749x; 1.2749x over previous
#include <cuda_runtime.h>
#include <cuda_bf16.h>
#include <cstdint>

#define NN  100000
#define EE  800000
#define DD  96
#define NRD 102   // D + XD

// ---- scratch (device globals; no allocation allowed) ----
__device__ __align__(16) float4 g_num4[NN * 24];
__device__ float  g_den[NN];
__device__ __align__(16) float g_P[NN * DD];
__device__ __align__(16) float g_Q[NN * DD];
__device__ __align__(16) uint4 g_W3hi[96 * 12];     // bf16 [96 o][96 k]
__device__ __align__(16) uint4 g_W3lo[96 * 12];
__device__ __align__(16) uint4 g_W12hi[192 * 16];   // bf16 [192 n][128 k pad]
__device__ __align__(16) uint4 g_W12lo[192 * 16];

__device__ __forceinline__ uint32_t smem_u32(const void* p) {
    uint32_t a;
    asm("{ .reg .u64 t; cvta.to.shared.u64 t, %1; cvt.u32.u64 %0, t; }" : "=r"(a) : "l"(p));
    return a;
}

// ---------------------------------------------------------------------------
// bf16 split helpers
// ---------------------------------------------------------------------------
__device__ __forceinline__ void split4(float4 v, uint2& hi, uint2& lo) {
    uint32_t h01, h23, l01, l23;
    asm("cvt.rn.bf16x2.f32 %0, %1, %2;" : "=r"(h01) : "f"(v.y), "f"(v.x));
    asm("cvt.rn.bf16x2.f32 %0, %1, %2;" : "=r"(h23) : "f"(v.w), "f"(v.z));
    float r0 = v.x - __uint_as_float(h01 << 16);
    float r1 = v.y - __uint_as_float(h01 & 0xFFFF0000u);
    float r2 = v.z - __uint_as_float(h23 << 16);
    float r3 = v.w - __uint_as_float(h23 & 0xFFFF0000u);
    asm("cvt.rn.bf16x2.f32 %0, %1, %2;" : "=r"(l01) : "f"(r1), "f"(r0));
    asm("cvt.rn.bf16x2.f32 %0, %1, %2;" : "=r"(l23) : "f"(r3), "f"(r2));
    hi = make_uint2(h01, h23); lo = make_uint2(l01, l23);
}
__device__ __forceinline__ void split2(float f0, float f1, uint32_t& hi, uint32_t& lo) {
    asm("cvt.rn.bf16x2.f32 %0, %1, %2;" : "=r"(hi) : "f"(f1), "f"(f0));
    float r0 = f0 - __uint_as_float(hi << 16);
    float r1 = f1 - __uint_as_float(hi & 0xFFFF0000u);
    asm("cvt.rn.bf16x2.f32 %0, %1, %2;" : "=r"(lo) : "f"(r1), "f"(r0));
}

// ---------------------------------------------------------------------------
// K0: zero accumulators, write x cols; block 0 pre-splits W3 and W1|W2
// ---------------------------------------------------------------------------
__global__ void init_k(const float* __restrict__ x, float* __restrict__ node_out,
                       const float* __restrict__ W) {
    if (blockIdx.x == 0) {
        // W3 [96 o][96 k] -> bf16 hi/lo
        for (int i = threadIdx.x; i < 96 * 24; i += 256) {
            int o = i / 24, q = i % 24;
            float4 v = *(const float4*)(W + o * 300 + 204 + q * 4);
            uint2 hi, lo;
            split4(v, hi, lo);
            *((uint2*)g_W3hi + o * 24 + q) = hi;
            *((uint2*)g_W3lo + o * 24 + q) = lo;
        }
        // W1|W2 [192 n][102 k] -> bf16 hi/lo padded to 128 k
        for (int i = threadIdx.x; i < 192 * 64; i += 256) {
            int n = i >> 6, kp = i & 63, k = kp * 2;
            const float* src = (n < 96) ? (W + n * 300 + k) : (W + (n - 96) * 300 + 102 + k);
            float f0 = (k < 102) ? src[0] : 0.f;
            float f1 = (k + 1 < 102) ? src[1] : 0.f;
            uint32_t hi, lo;
            split2(f0, f1, hi, lo);
            ((uint32_t*)g_W12hi)[i] = hi;
            ((uint32_t*)g_W12lo)[i] = lo;
        }
    }
    int i = blockIdx.x * 256 + threadIdx.x;
    if (i < NN * 24) g_num4[i] = make_float4(0.f, 0.f, 0.f, 0.f);
    if (i < NN)      g_den[i] = 0.f;
    if (i < NN * 6)  node_out[(i / 6) * NRD + 96 + (i % 6)] = x[i];
}

// ---------------------------------------------------------------------------
__global__ void scatter_k(const int* __restrict__ ei,
                          const float* __restrict__ attr,
                          const float* __restrict__ mask) {
    int i = blockIdx.x * 256 + threadIdx.x;
    if (i >= EE * 24) return;
    int e = i / 24;
    int q = i - e * 24;
    int c = ei[EE + e];
    float m = mask[e];
    float4 v = *(const float4*)(attr + (size_t)e * 96 + q * 4);
    float* dst = ((float*)g_num4) + (size_t)c * 96 + q * 4;
    asm volatile("red.global.add.v4.f32 [%0], {%1,%2,%3,%4};"
                 :: "l"(dst), "f"(v.x * m), "f"(v.y * m), "f"(v.z * m), "f"(v.w * m)
                 : "memory");
    if (q == 0) atomicAdd(&g_den[c], m);
}

// ---------------------------------------------------------------------------
__global__ void finalize_k(float* __restrict__ node_out) {
    int i = blockIdx.x * 256 + threadIdx.x;
    if (i >= NN * 24) return;
    int n = i / 24;
    int q = i - n * 24;
    float inv = 1.f / (g_den[n] + 1.f);
    float4 v = g_num4[i];
    float* dst = node_out + (size_t)n * NRD + q * 4;
    dst[0] = v.x * inv; dst[1] = v.y * inv; dst[2] = v.z * inv; dst[3] = v.w * inv;
}

// ---------------------------------------------------------------------------
__global__ void blend_k(const int* __restrict__ change,
                        const int* __restrict__ is_support,
                        const int* __restrict__ tails,
                        const float* __restrict__ support_tail,
                        float* __restrict__ node_out) {
    if (change[0] == 0) return;
    const int TOT = 128 * NRD;
    int tid = threadIdx.x;
    float vals[13];
    int   addr[13];
    short dim[13];
    int cnt = 0;
    for (int i = tid; i < TOT; i += 1024) {
        int t = i / NRD, d = i - t * NRD;
        int node = tails[t];
        addr[cnt] = node * NRD + d;
        dim[cnt]  = (short)d;
        vals[cnt] = node_out[addr[cnt]];
        cnt++;
    }
    if (is_support[0]) {
        __shared__ float ssum[NRD];
        for (int d = tid; d < NRD; d += 1024) ssum[d] = 0.f;
        __syncthreads();
        for (int j = 0; j < cnt; j++) atomicAdd(&ssum[dim[j]], vals[j]);
        __syncthreads();
        for (int j = 0; j < cnt; j++)
            node_out[addr[j]] = ssum[dim[j]] * (1.f / 128.f);
    } else {
        __syncthreads();
        for (int j = 0; j < cnt; j++)
            node_out[addr[j]] = 0.1f * support_tail[dim[j]] + 0.9f * vals[j];
    }
}

// ---------------------------------------------------------------------------
// shared MMA helpers
// ---------------------------------------------------------------------------
__device__ __forceinline__ void ldsm4(uint32_t addr, uint32_t* r) {
    asm volatile("ldmatrix.sync.aligned.m8n8.x4.shared.b16 {%0,%1,%2,%3}, [%4];"
                 : "=r"(r[0]), "=r"(r[1]), "=r"(r[2]), "=r"(r[3]) : "r"(addr));
}
__device__ __forceinline__ void mma_bf16(float4& c, const uint32_t* a,
                                         uint32_t b0, uint32_t b1) {
    asm volatile(
        "mma.sync.aligned.m16n8k16.row.col.f32.bf16.bf16.f32 "
        "{%0,%1,%2,%3}, {%4,%5,%6,%7}, {%8,%9}, {%0,%1,%2,%3};"
        : "+f"(c.x), "+f"(c.y), "+f"(c.z), "+f"(c.w)
        : "r"(a[0]), "r"(a[1]), "r"(a[2]), "r"(a[3]), "r"(b0), "r"(b1));
}

#define RS 80           // row stride bytes (64B data + 16B pad)

// ---------------------------------------------------------------------------
// K4: P|Q fused GEMM via HMMA bf16 3-term split.
//   Tile: 64 nodes x 192 outs (P cols 0..95 = nh 0, Q = nh 1). K padded to 128.
// ---------------------------------------------------------------------------
__global__ __launch_bounds__(256, 2) void pq_mma(const float* __restrict__ node_rep) {
    __shared__ __align__(16) char sAhi[64 * RS];    //  5120 B
    __shared__ __align__(16) char sAlo[64 * RS];
    __shared__ __align__(16) char sBhi[192 * RS];   // 15360 B
    __shared__ __align__(16) char sBlo[192 * RS];

    int tid = threadIdx.x, lane = tid & 31, w = tid >> 5;
    int n0 = blockIdx.x * 64;
    int w4 = w & 3, nh = w >> 2;

    uint32_t aHi = smem_u32(sAhi), aLo = smem_u32(sAlo);
    uint32_t bHi = smem_u32(sBhi), bLo = smem_u32(sBlo);

    uint32_t aoff = (uint32_t)(w4 * 16 + (lane & 15)) * RS + ((lane >> 4) & 1) * 16;
    uint32_t boff = ((lane >> 4) & 1) * 8 * RS + (uint32_t)(lane & 7) * RS
                  + ((lane >> 3) & 1) * 16;

    float4 acc[12];
    #pragma unroll
    for (int t = 0; t < 12; t++) acc[t] = make_float4(0.f, 0.f, 0.f, 0.f);

    #pragma unroll
    for (int c = 0; c < 4; c++) {
        int kc0 = c * 32;
        if (c) __syncthreads();
        // A chunk: 64 rows x 32 k as bf16 hi/lo (zeros for pad / OOB rows)
        #pragma unroll
        for (int v = 0; v < 4; v++) {
            int f = tid + v * 256;               // 1024 = 64 rows x 16 pairs
            int r = f >> 4, j = f & 15;
            int k = kc0 + j * 2;
            int n = n0 + r;
            float2 val = (n < NN && k < 102)
                ? *(const float2*)(node_rep + (size_t)n * NRD + k)
                : make_float2(0.f, 0.f);
            uint32_t hi, lo;
            split2(val.x, val.y, hi, lo);
            int off = r * RS + j * 4;
            *(uint32_t*)(sAhi + off) = hi;
            *(uint32_t*)(sAlo + off) = lo;
        }
        // B chunk: 2 arrays x 192 rows x 4 uint4
        #pragma unroll
        for (int v = 0; v < 6; v++) {
            int f = tid + v * 256;
            int sel = f >= 768;
            int g = sel ? f - 768 : f;
            int o = g >> 2, q = g & 3;
            uint4 val = (sel ? g_W12lo : g_W12hi)[o * 16 + c * 4 + q];
            *(uint4*)((sel ? sBlo : sBhi) + o * RS + q * 16) = val;
        }
        __syncthreads();

        #pragma unroll
        for (int kc16 = 0; kc16 < 2; kc16++) {
            uint32_t ah[4], al[4];
            ldsm4(aHi + aoff + kc16 * 32, ah);
            ldsm4(aLo + aoff + kc16 * 32, al);
            #pragma unroll
            for (int tp = 0; tp < 6; tp++) {
                uint32_t bh[4], bl[4];
                uint32_t bo = (uint32_t)(nh * 96 + tp * 16) * RS + boff + kc16 * 32;
                ldsm4(bHi + bo, bh);
                ldsm4(bLo + bo, bl);
                mma_bf16(acc[tp * 2],     ah, bh[0], bh[1]);
                mma_bf16(acc[tp * 2],     ah, bl[0], bl[1]);
                mma_bf16(acc[tp * 2],     al, bh[0], bh[1]);
                mma_bf16(acc[tp * 2 + 1], ah, bh[2], bh[3]);
                mma_bf16(acc[tp * 2 + 1], ah, bl[2], bl[3]);
                mma_bf16(acc[tp * 2 + 1], al, bh[2], bh[3]);
            }
        }
    }

    float* outb = nh ? g_Q : g_P;
    int mrow = w4 * 16 + (lane >> 2);
    int kq = lane & 3;
    int node0 = n0 + mrow, node1 = node0 + 8;
    #pragma unroll
    for (int t = 0; t < 12; t++) {
        int col = t * 8 + kq * 2;
        if (node0 < NN)
            *(float2*)(outb + (size_t)node0 * 96 + col) = make_float2(acc[t].x, acc[t].y);
        if (node1 < NN)
            *(float2*)(outb + (size_t)node1 * 96 + col) = make_float2(acc[t].z, acc[t].w);
    }
}

// ---------------------------------------------------------------------------
// K5: edge_rep via HMMA bf16 3-term split — R6 chunked + register prefetch.
// ---------------------------------------------------------------------------
__global__ __launch_bounds__(256, 2) void edge_mma(const float* __restrict__ attr,
                                                   const float* __restrict__ b,
                                                   const int* __restrict__ ei,
                                                   float* __restrict__ out) {
    __shared__ __align__(16) char sAhi[128 * RS];   // 10240 B
    __shared__ __align__(16) char sAlo[128 * RS];
    __shared__ __align__(16) char sBhi[96 * RS];    //  7680 B
    __shared__ __align__(16) char sBlo[96 * RS];

    int tid = threadIdx.x, lane = tid & 31, w = tid >> 5;
    size_t e0 = (size_t)blockIdx.x * 128;

    uint32_t aHi = smem_u32(sAhi), aLo = smem_u32(sAlo);
    uint32_t bHi = smem_u32(sBhi), bLo = smem_u32(sBlo);

    uint32_t aoff = (uint32_t)(w * 16 + (lane & 15)) * RS + ((lane >> 4) & 1) * 16;
    uint32_t boff = ((lane >> 4) & 1) * 8 * RS + (uint32_t)(lane & 7) * RS
                  + ((lane >> 3) & 1) * 16;

    float4 acc[12];
    #pragma unroll
    for (int t = 0; t < 12; t++) acc[t] = make_float4(0.f, 0.f, 0.f, 0.f);

    float4 pa[4];
    uint4  pb[3];

    // prefetch chunk 0
    #pragma unroll
    for (int v = 0; v < 4; v++) {
        int f = tid + v * 256;
        int r = f >> 3, q4 = f & 7;
        pa[v] = *(const float4*)(attr + (e0 + r) * 96 + q4 * 4);
    }
    #pragma unroll
    for (int v = 0; v < 3; v++) {
        int f = tid + v * 256;
        int sel = f >= 384;
        int g = sel ? f - 384 : f;
        pb[v] = (sel ? g_W3lo : g_W3hi)[(g >> 2) * 12 + (g & 3)];
    }

    #pragma unroll
    for (int c = 0; c < 3; c++) {
        if (c) __syncthreads();                    // prev MMA reads done
        // store prefetched chunk
        #pragma unroll
        for (int v = 0; v < 4; v++) {
            int f = tid + v * 256;
            int r = f >> 3, q4 = f & 7;
            uint2 hi, lo;
            split4(pa[v], hi, lo);
            int off = r * RS + q4 * 8;
            *(uint2*)(sAhi + off) = hi;
            *(uint2*)(sAlo + off) = lo;
        }
        #pragma unroll
        for (int v = 0; v < 3; v++) {
            int f = tid + v * 256;
            int sel = f >= 384;
            int g = sel ? f - 384 : f;
            *(uint4*)((sel ? sBlo : sBhi) + (g >> 2) * RS + (g & 3) * 16) = pb[v];
        }
        __syncthreads();
        // prefetch next chunk while MMAs run
        if (c < 2) {
            int kc0 = (c + 1) * 32;
            int kq = kc0 >> 3;
            #pragma unroll
            for (int v = 0; v < 4; v++) {
                int f = tid + v * 256;
                int r = f >> 3, q4 = f & 7;
                pa[v] = *(const float4*)(attr + (e0 + r) * 96 + kc0 + q4 * 4);
            }
            #pragma unroll
            for (int v = 0; v < 3; v++) {
                int f = tid + v * 256;
                int sel = f >= 384;
                int g = sel ? f - 384 : f;
                pb[v] = (sel ? g_W3lo : g_W3hi)[(g >> 2) * 12 + kq + (g & 3)];
            }
        }
        #pragma unroll
        for (int kc16 = 0; kc16 < 2; kc16++) {
            uint32_t ah[4], al[4];
            ldsm4(aHi + aoff + kc16 * 32, ah);
            ldsm4(aLo + aoff + kc16 * 32, al);
            #pragma unroll
            for (int tp = 0; tp < 6; tp++) {
                uint32_t bh[4], bl[4];
                uint32_t bo = (uint32_t)(tp * 16) * RS + boff + kc16 * 32;
                ldsm4(bHi + bo, bh);
                ldsm4(bLo + bo, bl);
                mma_bf16(acc[tp * 2],     ah, bh[0], bh[1]);
                mma_bf16(acc[tp * 2],     ah, bl[0], bl[1]);
                mma_bf16(acc[tp * 2],     al, bh[0], bh[1]);
                mma_bf16(acc[tp * 2 + 1], ah, bh[2], bh[3]);
                mma_bf16(acc[tp * 2 + 1], ah, bl[2], bl[3]);
                mma_bf16(acc[tp * 2 + 1], al, bh[2], bh[3]);
            }
        }
    }

    // epilogue
    int mrow = w * 16 + (lane >> 2);
    int kq = lane & 3;
    int er0 = (int)e0 + mrow;
    int er1 = er0 + 8;
    int r0i = ei[er0], c0i = ei[EE + er0];
    int r1i = ei[er1], c1i = ei[EE + er1];
    const float* P0 = g_P + (size_t)r0i * 96;
    const float* Q0 = g_Q + (size_t)c0i * 96;
    const float* P1 = g_P + (size_t)r1i * 96;
    const float* Q1 = g_Q + (size_t)c1i * 96;
    float* o0 = out + (size_t)er0 * 96;
    float* o1 = out + (size_t)er1 * 96;
    #pragma unroll
    for (int t = 0; t < 12; t++) {
        int col = t * 8 + kq * 2;
        float2 bv = *(const float2*)(b + col);
        float2 p0 = *(const float2*)(P0 + col), q0 = *(const float2*)(Q0 + col);
        *(float2*)(o0 + col) = make_float2(acc[t].x + p0.x + q0.x + bv.x,
                                           acc[t].y + p0.y + q0.y + bv.y);
        float2 p1 = *(const float2*)(P1 + col), q1 = *(const float2*)(Q1 + col);
        *(float2*)(o1 + col) = make_float2(acc[t].z + p1.x + q1.x + bv.x,
                                           acc[t].w + p1.y + q1.y + bv.y);
    }
}

// ---------------------------------------------------------------------------
extern "C" void kernel_launch(void* const* d_in, const int* in_sizes, int n_in,
                              void* d_out, int out_size) {
    const int*   change = (const int*)d_in[0];
    const int*   is_sup = (const int*)d_in[1];
    const int*   tails  = (const int*)d_in[3];
    const float* x      = (const float*)d_in[4];
    const int*   ei     = (const int*)d_in[5];
    const float* attr   = (const float*)d_in[6];
    const float* mask   = (const float*)d_in[7];
    const float* stail  = (const float*)d_in[9];
    const float* W      = (const float*)d_in[10];
    const float* b      = (const float*)d_in[11];

    float* node_out = (float*)d_out;
    float* edge_out = node_out + (size_t)NN * NRD;

    init_k    <<<(NN * 24 + 255) / 256, 256>>>(x, node_out, W);
    scatter_k <<<(EE * 24 + 255) / 256, 256>>>(ei, attr, mask);
    finalize_k<<<(NN * 24 + 255) / 256, 256>>>(node_out);
    blend_k   <<<1, 1024>>>(change, is_sup, tails, stail, node_out);
    pq_mma    <<<(NN + 63) / 64, 256>>>(node_out);
    edge_mma  <<<EE / 128, 256>>>(attr, b, ei, edge_out);
}